// round 9
// baseline (speedup 1.0000x reference)
#include <cuda_runtime.h>
#include <cuda_fp16.h>
#include <cstdint>

#define EMB_DIM 300
#define KP      304                 // K padded to multiple of 16
#define NTOT    2048
#define MTOT    32768
#define MTILE   128
#define NCHUNK  256
#define NCHUNKS (NTOT / NCHUNK)     // 8
#define NPHASES (NCHUNKS * 4)       // 32 quarter-K phases
#define ASTR    312                 // halves per A row (conflict-free ldmatrix)
#define BSTR    264                 // halves per B row (264*2=528B, odd*16)
#define QROWS   80                  // k-rows per quarter (last quarter uses 64)
#define A_BYTES (MTILE * ASTR * 2)  // 79872
#define QBUF    (QROWS * BSTR * 2)  // 42240
#define SMEM_BYTES (A_BYTES + 2 * QBUF)   // 164352
#define SCALE 45.254833995939045f   // sqrt(2048)

__device__ __half g_Wh[KP * NTOT];  // fp16 W, K zero-padded
__device__ float  g_bs[NTOT];       // bias * scale

__global__ void prep(const float* __restrict__ W, const float* __restrict__ b) {
    int i = blockIdx.x * blockDim.x + threadIdx.x;
    if (i < KP * NTOT) {
        int k = i / NTOT, n = i % NTOT;
        g_Wh[i] = __float2half_rn((k < EMB_DIM) ? W[k * NTOT + n] : 0.0f);
    }
    if (i < NTOT) g_bs[i] = b[i] * SCALE;
}

__device__ __forceinline__ void ldm_x4(uint32_t* r, uint32_t a) {
    asm volatile("ldmatrix.sync.aligned.m8n8.x4.shared.b16 {%0,%1,%2,%3}, [%4];"
                 : "=r"(r[0]), "=r"(r[1]), "=r"(r[2]), "=r"(r[3]) : "r"(a));
}
__device__ __forceinline__ void ldm_x4_t(uint32_t* r, uint32_t a) {
    asm volatile("ldmatrix.sync.aligned.m8n8.x4.trans.shared.b16 {%0,%1,%2,%3}, [%4];"
                 : "=r"(r[0]), "=r"(r[1]), "=r"(r[2]), "=r"(r[3]) : "r"(a));
}
__device__ __forceinline__ void mma16816(float* d, const uint32_t* a, const uint32_t* b) {
    asm volatile("mma.sync.aligned.m16n8k16.row.col.f32.f16.f16.f32 "
                 "{%0,%1,%2,%3}, {%4,%5,%6,%7}, {%8,%9}, {%0,%1,%2,%3};"
                 : "+f"(d[0]), "+f"(d[1]), "+f"(d[2]), "+f"(d[3])
                 : "r"(a[0]), "r"(a[1]), "r"(a[2]), "r"(a[3]),
                   "r"(b[0]), "r"(b[1]));
}

// cp.async one quarter: k-rows [kr0, kr0+nrows) x cols [n0, n0+256)
__device__ __forceinline__ void cp_bq(uint32_t dstU, int n0, int kr0,
                                      int nrows, int tid) {
    int tot = nrows * 32;                       // uint4 per quarter
    for (int i = tid; i < tot; i += 512) {
        int r = i >> 5, j = i & 31;
        uint32_t dst = dstU + (uint32_t)r * (BSTR * 2) + (uint32_t)j * 16;
        size_t g = __cvta_generic_to_global(g_Wh + (size_t)(kr0 + r) * NTOT
                                            + n0 + 8 * j);
        asm volatile("cp.async.cg.shared.global [%0], [%1], 16;"
                     :: "r"(dst), "l"(g));
    }
}

// MMA over NSTEPS k-steps: warp tile m32 x n64, acc[2][8][4]
template <int NSTEPS>
__device__ __forceinline__ void mma_phase(uint32_t aBase, uint32_t bBase,
                                          float (&acc)[2][8][4]) {
    #pragma unroll
    for (int ks = 0; ks < NSTEPS; ++ks) {
        uint32_t af[2][4], bf[4][4];
        uint32_t kbA = (uint32_t)ks * 32;
        uint32_t kbB = (uint32_t)ks * 16 * (BSTR * 2);
        ldm_x4(af[0], aBase + kbA);
        ldm_x4(af[1], aBase + (uint32_t)(16 * ASTR) * 2 + kbA);
        #pragma unroll
        for (int p = 0; p < 4; ++p)
            ldm_x4_t(bf[p], bBase + (uint32_t)p * 32 + kbB);
        #pragma unroll
        for (int mt = 0; mt < 2; ++mt)
            #pragma unroll
            for (int nt = 0; nt < 8; ++nt) {
                uint32_t bb[2] = { bf[nt >> 1][(nt & 1) * 2],
                                   bf[nt >> 1][(nt & 1) * 2 + 1] };
                mma16816(acc[mt][nt], af[mt], bb);
            }
    }
}

__global__ __launch_bounds__(512, 1)
void gemm_kernel(const int* __restrict__ x, const float* __restrict__ emb,
                 float* __restrict__ out) {
    extern __shared__ __half sm[];
    __half* A_s = sm;                          // [MTILE][ASTR]
    const uint32_t smem_u = (uint32_t)__cvta_generic_to_shared(sm);
    const uint32_t bBuf[2] = { smem_u + A_BYTES, smem_u + A_BYTES + QBUF };

    const int tid = threadIdx.x;
    const int m0  = blockIdx.x * MTILE;

    // prologue: phases 0 and 1 of chunk 0 in flight, then A gather overlaps
    cp_bq(bBuf[0], 0, 0, QROWS, tid);
    asm volatile("cp.async.commit_group;" ::: "memory");
    cp_bq(bBuf[1], 0, QROWS, QROWS, tid);
    asm volatile("cp.async.commit_group;" ::: "memory");

    // ---- Gather A: 128 rows, 4 threads/row, fp32 -> fp16 ----
    {
        int r = tid >> 2;
        int token = x[m0 + r];
        const float4* src = (const float4*)(emb + (size_t)token * EMB_DIM);
        __half* dstrow = A_s + r * ASTR;
        #pragma unroll
        for (int i = 0; i < 19; ++i) {
            int j = (tid & 3) + 4 * i;          // 75 float4 per row
            if (j < 75) {
                float4 v = src[j];
                __half2* d2 = (__half2*)(dstrow + 4 * j);
                d2[0] = __floats2half2_rn(v.x, v.y);
                d2[1] = __floats2half2_rn(v.z, v.w);
            }
        }
        if (tid < MTILE) {                      // zero K pad 300..303
            __half2* zp = (__half2*)(A_s + tid * ASTR + 300);
            zp[0] = __half2half2(__float2half(0.0f));
            zp[1] = __half2half2(__float2half(0.0f));
        }
    }

    const int lane = tid & 31, wid = tid >> 5;   // 16 warps
    const int wm = wid & 3;         // 0..3 : m32 each
    const int wn = wid >> 2;        // 0..3 : n64 each
    const int bq = lane >> 3, rq = lane & 7;

    const uint32_t aBase0 = smem_u
        + (uint32_t)((wm * 32 + (bq & 1) * 8 + rq) * ASTR) * 2
        + (uint32_t)(bq >> 1) * 16;
    const uint32_t bLane = (uint32_t)(((bq & 1) * 8 + rq) * BSTR) * 2
                         + (uint32_t)(wn * 128 + (bq >> 1) * 16);

    float acc[2][8][4];

    #pragma unroll 1
    for (int ph = 0; ph < NPHASES; ++ph) {
        const int q  = ph & 3;                     // quarter in chunk
        const int nc = ph >> 2;                    // chunk

        if (q == 0) {
            #pragma unroll
            for (int mt = 0; mt < 2; ++mt)
                #pragma unroll
                for (int nt = 0; nt < 8; ++nt)
                    #pragma unroll
                    for (int qq = 0; qq < 4; ++qq) acc[mt][nt][qq] = 0.0f;
        }

        // current quarter's buffer resident? (keep 1 group in flight)
        asm volatile("cp.async.wait_group 1;" ::: "memory");
        __syncthreads();

        uint32_t aB = aBase0 + (uint32_t)(q * 5) * 32;     // kstep col offset
        uint32_t bB = bBuf[ph & 1] + bLane;
        if (q < 3) mma_phase<5>(aB, bB, acc);
        else       mma_phase<4>(aB, bB, acc);
        __syncthreads();                     // all warps done with this buffer

        // issue loads for phase ph+2 into the buffer just freed
        int ph2 = ph + 2;
        if (ph2 < NPHASES) {
            int q2 = ph2 & 3, nc2 = ph2 >> 2;
            cp_bq(bBuf[ph & 1], nc2 * NCHUNK, q2 * QROWS,
                  (q2 < 3) ? QROWS : (KP - 3 * QROWS), tid);
        }
        asm volatile("cp.async.commit_group;" ::: "memory");

        // ---- epilogue at chunk end (overlaps in-flight loads) ----
        if (q == 3) {
            int n0 = nc * NCHUNK;
            #pragma unroll
            for (int nt = 0; nt < 8; ++nt) {
                int col = n0 + wn * 64 + nt * 8 + (lane & 3) * 2;
                float2 cb = *(const float2*)(g_bs + col);
                #pragma unroll
                for (int mt = 0; mt < 2; ++mt) {
                    int row = m0 + wm * 32 + mt * 16 + (lane >> 2);
                    float2 v0 = { fmaf(acc[mt][nt][0], SCALE, cb.x),
                                  fmaf(acc[mt][nt][1], SCALE, cb.y) };
                    float2 v1 = { fmaf(acc[mt][nt][2], SCALE, cb.x),
                                  fmaf(acc[mt][nt][3], SCALE, cb.y) };
                    *(float2*)(out + (size_t)row * NTOT + col)       = v0;
                    *(float2*)(out + (size_t)(row + 8) * NTOT + col) = v1;
                }
            }
        }
    }
}

extern "C" void kernel_launch(void* const* d_in, const int* in_sizes, int n_in,
                              void* d_out, int out_size) {
    const int*   x    = (const int*)  d_in[0];
    const float* emb  = (const float*)d_in[1];
    const float* W    = (const float*)d_in[2];
    const float* bias = (const float*)d_in[3];
    float*       out  = (float*)      d_out;

    cudaFuncSetAttribute(gemm_kernel, cudaFuncAttributeMaxDynamicSharedMemorySize,
                         SMEM_BYTES);

    prep<<<(KP * NTOT + 255) / 256, 256>>>(W, bias);
    gemm_kernel<<<MTOT / MTILE, 512, SMEM_BYTES>>>(x, emb, out);
}